// round 13
// baseline (speedup 1.0000x reference)
#include <cuda_runtime.h>
#include <cuda_fp16.h>
#include <math.h>
#include <cstdint>

#define Bb 16
#define Cc 512
#define Hh 32
#define Ww 32
#define Nn 16384
#define Dd 32
#define Pp 16384   // Bb*Hh*Ww

// ---------------------------------------------------------------------------
// Scratch (__device__ globals; no allocation allowed)
// ---------------------------------------------------------------------------
__device__ float g_z[Pp * Dd];        // normalized projected latents [p][d]
__device__ float g_e[Nn * Dd];        // normalized codebook fp32 [n][d] (rows 128B aligned)
__device__ uint4 g_eb[Nn * 4];        // codebook fp16: [n][32 half] = 64 B/row
__device__ float g_tmax[(size_t)Pp * 512];  // per-position per-32-code-entry max (fp16 sims)
__device__ int   g_idx[Pp];
__device__ int   g_hist[Nn];
__device__ float g_loss_part[512];

// ---------------------------------------------------------------------------
// PTX helpers (baseline PTX only: no 'a'-features)
// ---------------------------------------------------------------------------
__device__ __forceinline__ uint32_t smem_u32(const void* p) {
    uint32_t a;
    asm("{ .reg .u64 t; cvta.to.shared.u64 t, %1; cvt.u32.u64 %0, t; }" : "=r"(a) : "l"(p));
    return a;
}
__device__ __forceinline__ void ldsm4(uint32_t* r, uint32_t addr) {
    asm volatile("ldmatrix.sync.aligned.m8n8.x4.shared.b16 {%0,%1,%2,%3}, [%4];"
                 : "=r"(r[0]), "=r"(r[1]), "=r"(r[2]), "=r"(r[3]) : "r"(addr));
}
__device__ __forceinline__ void mma16816(float* d, const uint32_t* a, const uint32_t* b) {
    asm volatile("mma.sync.aligned.m16n8k16.row.col.f32.f16.f16.f32 "
                 "{%0,%1,%2,%3}, {%4,%5,%6,%7}, {%8,%9}, {%0,%1,%2,%3};"
                 : "+f"(d[0]), "+f"(d[1]), "+f"(d[2]), "+f"(d[3])
                 : "r"(a[0]), "r"(a[1]), "r"(a[2]), "r"(a[3]), "r"(b[0]), "r"(b[1]));
}
__device__ __forceinline__ void cpasync16(uint32_t dst, const void* src) {
    asm volatile("cp.async.cg.shared.global [%0], [%1], 16;" :: "r"(dst), "l"(src));
}
#define CP_COMMIT() asm volatile("cp.async.commit_group;" ::: "memory")
#define CP_WAIT0()  asm volatile("cp.async.wait_group 0;" ::: "memory")
#define CP_WAIT1()  asm volatile("cp.async.wait_group 1;" ::: "memory")

__device__ __forceinline__ bool better(float xv, int xi, float yv, int yi) {
    return xv > yv || (xv == yv && xi < yi);
}

// ---------------------------------------------------------------------------
// K_prep_e: normalize codebook rows; fp32 copy + fp16 copy; zero hist slots.
// ---------------------------------------------------------------------------
__global__ void k_prep_e(const float* __restrict__ emb) {
    int warp = threadIdx.x >> 5, lane = threadIdx.x & 31;
    if (threadIdx.x < 8) g_hist[blockIdx.x * 8 + threadIdx.x] = 0;
    int n = blockIdx.x * 8 + warp;
    float v = emb[n * Dd + lane];
    float ss = v * v;
    #pragma unroll
    for (int o = 16; o; o >>= 1) ss += __shfl_xor_sync(0xffffffffu, ss, o);
    float rn = 1.0f / fmaxf(sqrtf(ss), 1e-6f);
    float zn = v * rn;
    g_e[n * Dd + lane] = zn;
    ((__half*)g_eb)[(size_t)n * 32 + lane] = __float2half(zn);
}

// ---------------------------------------------------------------------------
// K1: projection (1x1 conv C->D) + L2 normalize along D.
// Inner loop float4-ized: broadcast LDS.128 of proj rows, 4-cl unroll.
// ---------------------------------------------------------------------------
__global__ __launch_bounds__(256) void k_project(const float* __restrict__ enc,
                                                 const float* __restrict__ pw,
                                                 const float* __restrict__ pb) {
    __shared__ float enc_s[64][32];
    __shared__ __align__(16) float proj_s[32][64];
    __shared__ float z_s[32][33];
    __shared__ float rn_s[32];

    int bh  = blockIdx.x;
    int tid = threadIdx.x;
    int w   = tid & 31;
    int dg  = tid >> 5;

    const float* encbase = enc + (size_t)(bh >> 5) * Cc * Hh * Ww + (size_t)(bh & 31) * Ww;

    float acc[4] = {0.f, 0.f, 0.f, 0.f};

    for (int c0 = 0; c0 < Cc; c0 += 64) {
        #pragma unroll
        for (int k = 0; k < 2; k++) {
            int i = tid + 256 * k;            // 0..511
            int cl = i >> 3, v = i & 7;
            *(float4*)&enc_s[cl][v * 4] =
                *(const float4*)(encbase + (size_t)(c0 + cl) * (Hh * Ww) + v * 4);
        }
        #pragma unroll
        for (int k = 0; k < 2; k++) {
            int i = tid + 256 * k;
            int d = i >> 4, c4 = i & 15;
            *(float4*)&proj_s[d][c4 * 4] =
                *(const float4*)(pw + d * Cc + c0 + c4 * 4);
        }
        __syncthreads();
        #pragma unroll
        for (int cl4 = 0; cl4 < 64; cl4 += 4) {
            float e0 = enc_s[cl4][w],     e1 = enc_s[cl4 + 1][w];
            float e2 = enc_s[cl4 + 2][w], e3 = enc_s[cl4 + 3][w];
            #pragma unroll
            for (int j = 0; j < 4; j++) {
                float4 p4 = *(const float4*)&proj_s[dg + 8 * j][cl4];
                acc[j] += p4.x * e0 + p4.y * e1 + p4.z * e2 + p4.w * e3;
            }
        }
        __syncthreads();
    }
    #pragma unroll
    for (int j = 0; j < 4; j++) z_s[dg + 8 * j][w] = acc[j] + pb[dg + 8 * j];
    __syncthreads();

    if (tid < 32) {
        float ss = 0.f;
        #pragma unroll
        for (int d = 0; d < 32; d++) { float v = z_s[d][tid]; ss += v * v; }
        rn_s[tid] = 1.0f / fmaxf(sqrtf(ss), 1e-6f);
    }
    __syncthreads();

    for (int i = tid; i < 1024; i += 256) {
        int ww = i >> 5, d = i & 31;
        g_z[((size_t)bh * 32 + ww) * Dd + d] = z_s[d][ww] * rn_s[ww];
    }
}

// ---------------------------------------------------------------------------
// K2: single-term fp16 HMMA sims (K=32); per-position per-32-code-entry MAX.
// (unchanged from the 206.9-us round-12 config)
// ---------------------------------------------------------------------------
#define A_BYTES   5120                        // 64 * 80
#define B_BYTES   10240                       // 128 * 80
#define SIMS_SMEM (A_BYTES + 3 * B_BYTES)     // 35840

__global__ __launch_bounds__(256, 2) void k_sims() {
    extern __shared__ __align__(16) char sm[];
    __half* As = (__half*)sm;                 // stride 40 half = 80 B
    uint32_t sbase = smem_u32(sm);

    int tid  = threadIdx.x;
    int lane = tid & 31;
    int w    = tid >> 5;      // 0..7
    int rg   = w & 3;         // row group (16 positions)
    int nh   = w >> 2;        // n-half (64 codes)
    int tg   = lane & 3;
    int gr   = lane >> 2;     // row-in-group 0..7
    int pbase = blockIdx.x * 64;

    for (int i = tid; i < 64 * 32; i += 256) {
        int row = i >> 5, d = i & 31;
        As[row * 40 + d] = __float2half(g_z[(size_t)(pbase + row) * Dd + d]);
    }

    uint32_t cprow = (uint32_t)(tid >> 1);
    uint32_t cphalf = (uint32_t)((tid & 1) * 32);
    uint32_t srcBase = cprow * 64 + cphalf;
    uint32_t dstBase = cprow * 80 + cphalf;

    const char* ebase = (const char*)g_eb;
    #pragma unroll
    for (int j = 0; j < 2; j++)
        cpasync16(sbase + A_BYTES + dstBase + j * 16, ebase + srcBase + j * 16);
    CP_COMMIT();
    #pragma unroll
    for (int j = 0; j < 2; j++)
        cpasync16(sbase + A_BYTES + B_BYTES + dstBase + j * 16,
                  ebase + 8192 + srcBase + j * 16);
    CP_COMMIT();
    __syncthreads();

    uint32_t afr[2][4];
    int q = lane >> 3, r = lane & 7;
    {
        uint32_t abase = sbase + (uint32_t)((rg * 16 + (q & 1) * 8 + r) * 80
                                            + (q >> 1) * 16);
        #pragma unroll
        for (int kk = 0; kk < 2; kk++) ldsm4(afr[kk], abase + kk * 32);
    }
    uint32_t brow_off = (uint32_t)((nh * 64 + (q >> 1) * 8 + r) * 80 + (q & 1) * 16);

    for (int t = 0; t < 128; t++) {
        if (t < 126) CP_WAIT1(); else CP_WAIT0();
        __syncthreads();
        if (t + 2 < 128) {
            const char* src = ebase + (size_t)(t + 2) * 8192 + srcBase;
            uint32_t dst = sbase + A_BYTES + (uint32_t)(((t + 2) % 3) * B_BYTES) + dstBase;
            #pragma unroll
            for (int j = 0; j < 2; j++)
                cpasync16(dst + j * 16, src + j * 16);
            CP_COMMIT();
        }

        uint32_t bb = sbase + A_BYTES + (uint32_t)((t % 3) * B_BYTES) + brow_off;
        float acc[8][4];
        #pragma unroll
        for (int nb = 0; nb < 8; nb++)
            #pragma unroll
            for (int i = 0; i < 4; i++) acc[nb][i] = 0.f;

        #pragma unroll
        for (int j = 0; j < 4; j++) {          // four n16 groups
            uint32_t bbj = bb + (uint32_t)j * (16 * 80);
            uint32_t b0[4], b1[4];
            ldsm4(b0, bbj);
            ldsm4(b1, bbj + 32);
            mma16816(acc[2*j],   afr[0], b0); mma16816(acc[2*j+1], afr[0], b0 + 2);
            mma16816(acc[2*j],   afr[1], b1); mma16816(acc[2*j+1], afr[1], b1 + 2);
        }

        float mA0, mA1, mB0, mB1;
        {
            float a0 = fmaxf(fmaxf(acc[0][0], acc[0][1]), fmaxf(acc[1][0], acc[1][1]));
            float a1 = fmaxf(fmaxf(acc[2][0], acc[2][1]), fmaxf(acc[3][0], acc[3][1]));
            mA0 = fmaxf(a0, a1);
            float a2 = fmaxf(fmaxf(acc[4][0], acc[4][1]), fmaxf(acc[5][0], acc[5][1]));
            float a3 = fmaxf(fmaxf(acc[6][0], acc[6][1]), fmaxf(acc[7][0], acc[7][1]));
            mA1 = fmaxf(a2, a3);
            float b0 = fmaxf(fmaxf(acc[0][2], acc[0][3]), fmaxf(acc[1][2], acc[1][3]));
            float b1 = fmaxf(fmaxf(acc[2][2], acc[2][3]), fmaxf(acc[3][2], acc[3][3]));
            mB0 = fmaxf(b0, b1);
            float b2 = fmaxf(fmaxf(acc[4][2], acc[4][3]), fmaxf(acc[5][2], acc[5][3]));
            float b3 = fmaxf(fmaxf(acc[6][2], acc[6][3]), fmaxf(acc[7][2], acc[7][3]));
            mB1 = fmaxf(b2, b3);
        }
        mA0 = fmaxf(mA0, __shfl_xor_sync(0xffffffffu, mA0, 1));
        mA0 = fmaxf(mA0, __shfl_xor_sync(0xffffffffu, mA0, 2));
        mA1 = fmaxf(mA1, __shfl_xor_sync(0xffffffffu, mA1, 1));
        mA1 = fmaxf(mA1, __shfl_xor_sync(0xffffffffu, mA1, 2));
        mB0 = fmaxf(mB0, __shfl_xor_sync(0xffffffffu, mB0, 1));
        mB0 = fmaxf(mB0, __shfl_xor_sync(0xffffffffu, mB0, 2));
        mB1 = fmaxf(mB1, __shfl_xor_sync(0xffffffffu, mB1, 1));
        mB1 = fmaxf(mB1, __shfl_xor_sync(0xffffffffu, mB1, 2));

        if (tg == 0) {
            int posA = rg * 16 + gr;                        // posB = posA + 8
            size_t ba = (size_t)(pbase + posA) * 512 + t * 4 + nh * 2;
            *(float2*)&g_tmax[ba] = make_float2(mA0, mA1);
            size_t bbx = ba + (size_t)8 * 512;
            *(float2*)&g_tmax[bbx] = make_float2(mB0, mB1);
        }
    }
}

// ---------------------------------------------------------------------------
// K_pass2: adaptive exact rescore.
// fp16 sim error eps <= ~1e-3 (inputs unit-norm; products exact in f32 accum).
// Any code that can beat the approx max v1 lies in an entry with
// approx-max >= v1 - 2*eps; rescore every entry with max >= v1 - 3e-3.
// Expected ~1.07 entries/position. One warp per position.
// ---------------------------------------------------------------------------
__global__ __launch_bounds__(256) void k_pass2() {
    __shared__ float zs[8][32];
    int tid  = threadIdx.x;
    int wp   = tid >> 5;
    int lane = tid & 31;
    int p    = blockIdx.x * 8 + wp;

    zs[wp][lane] = g_z[(size_t)p * Dd + lane];
    __syncwarp();

    // ---- load this lane's 16 entry maxima; warp max v1 ----
    const float4* tm = (const float4*)(g_tmax + (size_t)p * 512 + lane * 16);
    float ev[16];
    float v1 = -3e38f;
    #pragma unroll
    for (int qq = 0; qq < 4; qq++) {
        float4 f = tm[qq];
        ev[qq * 4 + 0] = f.x; ev[qq * 4 + 1] = f.y;
        ev[qq * 4 + 2] = f.z; ev[qq * 4 + 3] = f.w;
        v1 = fmaxf(v1, fmaxf(fmaxf(f.x, f.y), fmaxf(f.z, f.w)));
    }
    #pragma unroll
    for (int o = 16; o; o >>= 1) v1 = fmaxf(v1, __shfl_xor_sync(0xffffffffu, v1, o));

    // ---- qualifying-entry bitmask per lane ----
    float thr = v1 - 3e-3f;
    uint32_t mymask = 0;
    #pragma unroll
    for (int j = 0; j < 16; j++)
        if (ev[j] >= thr) mymask |= (1u << j);

    // ---- rescore loop: one entry (32 codes) per iteration ----
    int cg = lane >> 2, qt = lane & 3;
    float zq[8];
    #pragma unroll
    for (int j = 0; j < 8; j++) zq[j] = zs[wp][qt * 8 + j];

    float bv = -3e38f;
    int   bi = 0x7fffffff;
    for (;;) {
        uint32_t act = __ballot_sync(0xffffffffu, mymask != 0);
        if (!act) break;
        int src = __ffs(act) - 1;
        uint32_t m = __shfl_sync(0xffffffffu, mymask, src);
        int j = __ffs(m) - 1;
        if (lane == src) mymask &= mymask - 1;
        int e = src * 16 + j;
        #pragma unroll
        for (int it = 0; it < 4; it++) {
            int c = e * 32 + it * 8 + cg;
            const float4* er = (const float4*)(g_e + (size_t)c * Dd + qt * 8);
            float4 a = er[0], b = er[1];
            float s = a.x * zq[0] + a.y * zq[1] + a.z * zq[2] + a.w * zq[3]
                    + b.x * zq[4] + b.y * zq[5] + b.z * zq[6] + b.w * zq[7];
            s += __shfl_xor_sync(0xffffffffu, s, 1);
            s += __shfl_xor_sync(0xffffffffu, s, 2);
            if (better(s, c, bv, bi)) { bv = s; bi = c; }
        }
    }
    #pragma unroll
    for (int o = 16; o >= 4; o >>= 1) {
        float ov = __shfl_xor_sync(0xffffffffu, bv, o);
        int   oi = __shfl_xor_sync(0xffffffffu, bi, o);
        if (better(ov, oi, bv, bi)) { bv = ov; bi = oi; }
    }
    if (lane == 0) {
        g_idx[p] = bi;
        atomicAdd(&g_hist[bi], 1);
    }
}

// ---------------------------------------------------------------------------
// K3: gather latents, quantization-loss partial, expand D->C, write out.
// ---------------------------------------------------------------------------
__global__ __launch_bounds__(256) void k_output(const float* __restrict__ ew,
                                                const float* __restrict__ eb,
                                                float* __restrict__ out) {
    __shared__ float lat_s[32][33];
    __shared__ __align__(16) float exp_s[64][32];
    __shared__ float red[256];

    int bh  = blockIdx.x;
    int b   = bh >> 5, h = bh & 31;
    int tid = threadIdx.x;
    int pbase = bh * 32;

    float lsum = 0.f;
    for (int i = tid; i < 1024; i += 256) {
        int ww = i >> 5, d = i & 31;
        int ix = g_idx[pbase + ww];
        float lv = g_e[(size_t)ix * Dd + d];
        lat_s[ww][d] = lv;
        float dz = g_z[((size_t)pbase + ww) * Dd + d] - lv;
        lsum += dz * dz;
    }
    red[tid] = lsum;
    __syncthreads();
    for (int s = 128; s; s >>= 1) {
        if (tid < s) red[tid] += red[tid + s];
        __syncthreads();
    }
    if (tid == 0) g_loss_part[bh] = red[0];

    int w   = tid & 31;
    int cg8 = tid >> 5;

    float latr[32];
    #pragma unroll
    for (int d = 0; d < 32; d++) latr[d] = lat_s[w][d];

    for (int c0 = 0; c0 < Cc; c0 += 64) {
        __syncthreads();
        #pragma unroll
        for (int k = 0; k < 2; k++) {
            int i = tid + 256 * k;           // 0..511
            int cl = i >> 3, v = i & 7;
            *(float4*)&exp_s[cl][v * 4] =
                *(const float4*)(ew + (size_t)(c0 + cl) * Dd + v * 4);
        }
        __syncthreads();
        #pragma unroll
        for (int jj = 0; jj < 8; jj++) {
            int cl = cg8 + 8 * jj;
            int c  = c0 + cl;
            float s = eb[c];
            #pragma unroll
            for (int d4 = 0; d4 < 8; d4++) {
                float4 e4 = *(const float4*)&exp_s[cl][d4 * 4];
                s += e4.x * latr[4*d4] + e4.y * latr[4*d4+1]
                   + e4.z * latr[4*d4+2] + e4.w * latr[4*d4+3];
            }
            out[(((size_t)b * Cc + c) * Hh + h) * Ww + w] = s;
        }
    }
}

// ---------------------------------------------------------------------------
// K4: final scalars — loss mean and perplexity. 1024 threads.
// ---------------------------------------------------------------------------
__global__ __launch_bounds__(1024) void k_scalars(float* __restrict__ out, int osz) {
    __shared__ float red[1024];
    int tid = threadIdx.x;

    float s = (tid < 512) ? g_loss_part[tid] : 0.f;
    red[tid] = s;
    __syncthreads();
    for (int st = 512; st; st >>= 1) {
        if (tid < st) red[tid] += red[tid + st];
        __syncthreads();
    }
    if (tid == 0) out[osz - 2] = red[0] / (float)(Pp * Dd);
    __syncthreads();

    float e = 0.f;
    const float inv = 1.0f / (float)Pp;
    for (int i = tid; i < Nn; i += 1024) {
        int c = g_hist[i];
        if (c > 0) {
            float u = (float)c * inv;
            e -= u * logf(u + 1e-6f);
        }
    }
    red[tid] = e;
    __syncthreads();
    for (int st = 512; st; st >>= 1) {
        if (tid < st) red[tid] += red[tid + st];
        __syncthreads();
    }
    if (tid == 0) out[osz - 1] = expf(red[0]);
}

// ---------------------------------------------------------------------------
extern "C" void kernel_launch(void* const* d_in, const int* in_sizes, int n_in,
                              void* d_out, int out_size) {
    const float* enc = (const float*)d_in[0];   // encodings [B,C,H,W]
    const float* emb = (const float*)d_in[1];   // emb_weight [N,D]
    const float* pw  = (const float*)d_in[2];   // proj_w [D,C]
    const float* pb  = (const float*)d_in[3];   // proj_b [D]
    const float* ew  = (const float*)d_in[4];   // exp_w [C,D]
    const float* eb  = (const float*)d_in[5];   // exp_b [C]
    float* out = (float*)d_out;

    cudaFuncSetAttribute(k_sims, cudaFuncAttributeMaxDynamicSharedMemorySize, SIMS_SMEM);

    k_prep_e<<<Nn / 8, 256>>>(emb);
    k_project<<<Bb * Hh, 256>>>(enc, pw, pb);
    k_sims<<<Pp / 64, 256, SIMS_SMEM>>>();
    k_pass2<<<Pp / 8, 256>>>();
    k_output<<<Bb * Hh, 256>>>(ew, eb, out);
    k_scalars<<<1, 1024>>>(out, out_size);
}

// round 14
// speedup vs baseline: 1.3496x; 1.3496x over previous
#include <cuda_runtime.h>
#include <cuda_fp16.h>
#include <math.h>
#include <cstdint>

#define Bb 16
#define Cc 512
#define Hh 32
#define Ww 32
#define Nn 16384
#define Dd 32
#define Pp 16384   // Bb*Hh*Ww

// ---------------------------------------------------------------------------
// Scratch (__device__ globals; no allocation allowed)
// ---------------------------------------------------------------------------
__device__ float g_z[Pp * Dd];        // normalized projected latents [p][d]
__device__ float g_e[Nn * Dd];        // normalized codebook fp32 [n][d] (rows 128B aligned)
__device__ uint4 g_eb[Nn * 4];        // codebook fp16: [n][32 half] = 64 B/row
__device__ float g_tmax[(size_t)Pp * 512];  // per-position per-32-code-entry max (fp16 sims)
__device__ int   g_idx[Pp];
__device__ int   g_hist[Nn];
__device__ float g_loss_part[512];

// ---------------------------------------------------------------------------
// PTX helpers (baseline PTX only: no 'a'-features)
// ---------------------------------------------------------------------------
__device__ __forceinline__ uint32_t smem_u32(const void* p) {
    uint32_t a;
    asm("{ .reg .u64 t; cvta.to.shared.u64 t, %1; cvt.u32.u64 %0, t; }" : "=r"(a) : "l"(p));
    return a;
}
__device__ __forceinline__ void ldsm4(uint32_t* r, uint32_t addr) {
    asm volatile("ldmatrix.sync.aligned.m8n8.x4.shared.b16 {%0,%1,%2,%3}, [%4];"
                 : "=r"(r[0]), "=r"(r[1]), "=r"(r[2]), "=r"(r[3]) : "r"(addr));
}
__device__ __forceinline__ void mma16816(float* d, const uint32_t* a, const uint32_t* b) {
    asm volatile("mma.sync.aligned.m16n8k16.row.col.f32.f16.f16.f32 "
                 "{%0,%1,%2,%3}, {%4,%5,%6,%7}, {%8,%9}, {%0,%1,%2,%3};"
                 : "+f"(d[0]), "+f"(d[1]), "+f"(d[2]), "+f"(d[3])
                 : "r"(a[0]), "r"(a[1]), "r"(a[2]), "r"(a[3]), "r"(b[0]), "r"(b[1]));
}
__device__ __forceinline__ void cpasync16(uint32_t dst, const void* src) {
    asm volatile("cp.async.cg.shared.global [%0], [%1], 16;" :: "r"(dst), "l"(src));
}
#define CP_COMMIT() asm volatile("cp.async.commit_group;" ::: "memory")
#define CP_WAIT0()  asm volatile("cp.async.wait_group 0;" ::: "memory")
#define CP_WAIT1()  asm volatile("cp.async.wait_group 1;" ::: "memory")

__device__ __forceinline__ bool better(float xv, int xi, float yv, int yi) {
    return xv > yv || (xv == yv && xi < yi);
}

// ---------------------------------------------------------------------------
// K_zero: clear histogram (keeps k_sims in the ncu capture slot)
// ---------------------------------------------------------------------------
__global__ void k_zero_hist() {
    g_hist[blockIdx.x * 256 + threadIdx.x] = 0;
}

// ---------------------------------------------------------------------------
// K_prep_e: normalize codebook rows; fp32 copy + single fp16 copy.
// ---------------------------------------------------------------------------
__global__ void k_prep_e(const float* __restrict__ emb) {
    int warp = threadIdx.x >> 5, lane = threadIdx.x & 31;
    int n = blockIdx.x * 8 + warp;
    float v = emb[n * Dd + lane];
    float ss = v * v;
    #pragma unroll
    for (int o = 16; o; o >>= 1) ss += __shfl_xor_sync(0xffffffffu, ss, o);
    float rn = 1.0f / fmaxf(sqrtf(ss), 1e-6f);
    float zn = v * rn;
    g_e[n * Dd + lane] = zn;
    ((__half*)g_eb)[(size_t)n * 32 + lane] = __float2half(zn);
}

// ---------------------------------------------------------------------------
// K1: projection (1x1 conv C->D) + L2 normalize along D.
// (exact round-12 version)
// ---------------------------------------------------------------------------
__global__ __launch_bounds__(256) void k_project(const float* __restrict__ enc,
                                                 const float* __restrict__ pw,
                                                 const float* __restrict__ pb) {
    __shared__ float enc_s[64][32];
    __shared__ float proj_s[32][64];
    __shared__ float z_s[32][33];
    __shared__ float rn_s[32];

    int bh  = blockIdx.x;
    int tid = threadIdx.x;
    int w   = tid & 31;
    int dg  = tid >> 5;

    const float* encbase = enc + (size_t)(bh >> 5) * Cc * Hh * Ww + (size_t)(bh & 31) * Ww;

    float acc[4] = {0.f, 0.f, 0.f, 0.f};

    for (int c0 = 0; c0 < Cc; c0 += 64) {
        #pragma unroll
        for (int k = 0; k < 2; k++) {
            int i = tid + 256 * k;            // 0..511
            int cl = i >> 3, v = i & 7;
            *(float4*)&enc_s[cl][v * 4] =
                *(const float4*)(encbase + (size_t)(c0 + cl) * (Hh * Ww) + v * 4);
        }
        #pragma unroll
        for (int k = 0; k < 2; k++) {
            int i = tid + 256 * k;
            int d = i >> 4, c4 = i & 15;
            *(float4*)&proj_s[d][c4 * 4] =
                *(const float4*)(pw + d * Cc + c0 + c4 * 4);
        }
        __syncthreads();
        #pragma unroll 16
        for (int cl = 0; cl < 64; cl++) {
            float ev = enc_s[cl][w];
            #pragma unroll
            for (int j = 0; j < 4; j++) acc[j] += proj_s[dg + 8 * j][cl] * ev;
        }
        __syncthreads();
    }
    #pragma unroll
    for (int j = 0; j < 4; j++) z_s[dg + 8 * j][w] = acc[j] + pb[dg + 8 * j];
    __syncthreads();

    if (tid < 32) {
        float ss = 0.f;
        #pragma unroll
        for (int d = 0; d < 32; d++) { float v = z_s[d][tid]; ss += v * v; }
        rn_s[tid] = 1.0f / fmaxf(sqrtf(ss), 1e-6f);
    }
    __syncthreads();

    for (int i = tid; i < 1024; i += 256) {
        int ww = i >> 5, d = i & 31;
        g_z[((size_t)bh * 32 + ww) * Dd + d] = z_s[d][ww] * rn_s[ww];
    }
}

// ---------------------------------------------------------------------------
// K2: single-term fp16 HMMA sims (K=32); per-position per-32-code-entry MAX.
// (exact round-12 version — 101.9 us measured)
// ---------------------------------------------------------------------------
#define A_BYTES   5120                        // 64 * 80
#define B_BYTES   10240                       // 128 * 80
#define SIMS_SMEM (A_BYTES + 3 * B_BYTES)     // 35840

__global__ __launch_bounds__(256, 2) void k_sims() {
    extern __shared__ __align__(16) char sm[];
    __half* As = (__half*)sm;                 // stride 40 half = 80 B
    uint32_t sbase = smem_u32(sm);

    int tid  = threadIdx.x;
    int lane = tid & 31;
    int w    = tid >> 5;      // 0..7
    int rg   = w & 3;         // row group (16 positions)
    int nh   = w >> 2;        // n-half (64 codes)
    int tg   = lane & 3;
    int gr   = lane >> 2;     // row-in-group 0..7
    int pbase = blockIdx.x * 64;

    for (int i = tid; i < 64 * 32; i += 256) {
        int row = i >> 5, d = i & 31;
        As[row * 40 + d] = __float2half(g_z[(size_t)(pbase + row) * Dd + d]);
    }

    uint32_t cprow = (uint32_t)(tid >> 1);
    uint32_t cphalf = (uint32_t)((tid & 1) * 32);
    uint32_t srcBase = cprow * 64 + cphalf;
    uint32_t dstBase = cprow * 80 + cphalf;

    const char* ebase = (const char*)g_eb;
    #pragma unroll
    for (int j = 0; j < 2; j++)
        cpasync16(sbase + A_BYTES + dstBase + j * 16, ebase + srcBase + j * 16);
    CP_COMMIT();
    #pragma unroll
    for (int j = 0; j < 2; j++)
        cpasync16(sbase + A_BYTES + B_BYTES + dstBase + j * 16,
                  ebase + 8192 + srcBase + j * 16);
    CP_COMMIT();
    __syncthreads();

    uint32_t afr[2][4];
    int q = lane >> 3, r = lane & 7;
    {
        uint32_t abase = sbase + (uint32_t)((rg * 16 + (q & 1) * 8 + r) * 80
                                            + (q >> 1) * 16);
        #pragma unroll
        for (int kk = 0; kk < 2; kk++) ldsm4(afr[kk], abase + kk * 32);
    }
    uint32_t brow_off = (uint32_t)((nh * 64 + (q >> 1) * 8 + r) * 80 + (q & 1) * 16);

    for (int t = 0; t < 128; t++) {
        if (t < 126) CP_WAIT1(); else CP_WAIT0();
        __syncthreads();
        if (t + 2 < 128) {
            const char* src = ebase + (size_t)(t + 2) * 8192 + srcBase;
            uint32_t dst = sbase + A_BYTES + (uint32_t)(((t + 2) % 3) * B_BYTES) + dstBase;
            #pragma unroll
            for (int j = 0; j < 2; j++)
                cpasync16(dst + j * 16, src + j * 16);
            CP_COMMIT();
        }

        uint32_t bb = sbase + A_BYTES + (uint32_t)((t % 3) * B_BYTES) + brow_off;
        float acc[8][4];
        #pragma unroll
        for (int nb = 0; nb < 8; nb++)
            #pragma unroll
            for (int i = 0; i < 4; i++) acc[nb][i] = 0.f;

        #pragma unroll
        for (int j = 0; j < 4; j++) {          // four n16 groups
            uint32_t bbj = bb + (uint32_t)j * (16 * 80);
            uint32_t b0[4], b1[4];
            ldsm4(b0, bbj);
            ldsm4(b1, bbj + 32);
            mma16816(acc[2*j],   afr[0], b0); mma16816(acc[2*j+1], afr[0], b0 + 2);
            mma16816(acc[2*j],   afr[1], b1); mma16816(acc[2*j+1], afr[1], b1 + 2);
        }

        float mA0, mA1, mB0, mB1;
        {
            float a0 = fmaxf(fmaxf(acc[0][0], acc[0][1]), fmaxf(acc[1][0], acc[1][1]));
            float a1 = fmaxf(fmaxf(acc[2][0], acc[2][1]), fmaxf(acc[3][0], acc[3][1]));
            mA0 = fmaxf(a0, a1);
            float a2 = fmaxf(fmaxf(acc[4][0], acc[4][1]), fmaxf(acc[5][0], acc[5][1]));
            float a3 = fmaxf(fmaxf(acc[6][0], acc[6][1]), fmaxf(acc[7][0], acc[7][1]));
            mA1 = fmaxf(a2, a3);
            float b0 = fmaxf(fmaxf(acc[0][2], acc[0][3]), fmaxf(acc[1][2], acc[1][3]));
            float b1 = fmaxf(fmaxf(acc[2][2], acc[2][3]), fmaxf(acc[3][2], acc[3][3]));
            mB0 = fmaxf(b0, b1);
            float b2 = fmaxf(fmaxf(acc[4][2], acc[4][3]), fmaxf(acc[5][2], acc[5][3]));
            float b3 = fmaxf(fmaxf(acc[6][2], acc[6][3]), fmaxf(acc[7][2], acc[7][3]));
            mB1 = fmaxf(b2, b3);
        }
        mA0 = fmaxf(mA0, __shfl_xor_sync(0xffffffffu, mA0, 1));
        mA0 = fmaxf(mA0, __shfl_xor_sync(0xffffffffu, mA0, 2));
        mA1 = fmaxf(mA1, __shfl_xor_sync(0xffffffffu, mA1, 1));
        mA1 = fmaxf(mA1, __shfl_xor_sync(0xffffffffu, mA1, 2));
        mB0 = fmaxf(mB0, __shfl_xor_sync(0xffffffffu, mB0, 1));
        mB0 = fmaxf(mB0, __shfl_xor_sync(0xffffffffu, mB0, 2));
        mB1 = fmaxf(mB1, __shfl_xor_sync(0xffffffffu, mB1, 1));
        mB1 = fmaxf(mB1, __shfl_xor_sync(0xffffffffu, mB1, 2));

        if (tg == 0) {
            int posA = rg * 16 + gr;                        // posB = posA + 8
            size_t ba = (size_t)(pbase + posA) * 512 + t * 4 + nh * 2;
            *(float2*)&g_tmax[ba] = make_float2(mA0, mA1);
            size_t bbx = ba + (size_t)8 * 512;
            *(float2*)&g_tmax[bbx] = make_float2(mB0, mB1);
        }
    }
}

// ---------------------------------------------------------------------------
// K_pass2: adaptive exact rescore (measured 26.1 us in round 13).
// fp16 sim error eps <= ~1e-3; rescore every entry with approx-max
// >= v1 - 3e-3 (provably contains every code that could beat v1).
// Expected ~1.07 entries/position. One warp per position.
// ---------------------------------------------------------------------------
__global__ __launch_bounds__(256) void k_pass2() {
    __shared__ float zs[8][32];
    int tid  = threadIdx.x;
    int wp   = tid >> 5;
    int lane = tid & 31;
    int p    = blockIdx.x * 8 + wp;

    zs[wp][lane] = g_z[(size_t)p * Dd + lane];
    __syncwarp();

    // ---- load this lane's 16 entry maxima; warp max v1 ----
    const float4* tm = (const float4*)(g_tmax + (size_t)p * 512 + lane * 16);
    float ev[16];
    float v1 = -3e38f;
    #pragma unroll
    for (int qq = 0; qq < 4; qq++) {
        float4 f = tm[qq];
        ev[qq * 4 + 0] = f.x; ev[qq * 4 + 1] = f.y;
        ev[qq * 4 + 2] = f.z; ev[qq * 4 + 3] = f.w;
        v1 = fmaxf(v1, fmaxf(fmaxf(f.x, f.y), fmaxf(f.z, f.w)));
    }
    #pragma unroll
    for (int o = 16; o; o >>= 1) v1 = fmaxf(v1, __shfl_xor_sync(0xffffffffu, v1, o));

    // ---- qualifying-entry bitmask per lane ----
    float thr = v1 - 3e-3f;
    uint32_t mymask = 0;
    #pragma unroll
    for (int j = 0; j < 16; j++)
        if (ev[j] >= thr) mymask |= (1u << j);

    // ---- rescore loop: one entry (32 codes) per iteration ----
    int cg = lane >> 2, qt = lane & 3;
    float zq[8];
    #pragma unroll
    for (int j = 0; j < 8; j++) zq[j] = zs[wp][qt * 8 + j];

    float bv = -3e38f;
    int   bi = 0x7fffffff;
    for (;;) {
        uint32_t act = __ballot_sync(0xffffffffu, mymask != 0);
        if (!act) break;
        int src = __ffs(act) - 1;
        uint32_t m = __shfl_sync(0xffffffffu, mymask, src);
        int j = __ffs(m) - 1;
        if (lane == src) mymask &= mymask - 1;
        int e = src * 16 + j;
        #pragma unroll
        for (int it = 0; it < 4; it++) {
            int c = e * 32 + it * 8 + cg;
            const float4* er = (const float4*)(g_e + (size_t)c * Dd + qt * 8);
            float4 a = er[0], b = er[1];
            float s = a.x * zq[0] + a.y * zq[1] + a.z * zq[2] + a.w * zq[3]
                    + b.x * zq[4] + b.y * zq[5] + b.z * zq[6] + b.w * zq[7];
            s += __shfl_xor_sync(0xffffffffu, s, 1);
            s += __shfl_xor_sync(0xffffffffu, s, 2);
            if (better(s, c, bv, bi)) { bv = s; bi = c; }
        }
    }
    #pragma unroll
    for (int o = 16; o >= 4; o >>= 1) {
        float ov = __shfl_xor_sync(0xffffffffu, bv, o);
        int   oi = __shfl_xor_sync(0xffffffffu, bi, o);
        if (better(ov, oi, bv, bi)) { bv = ov; bi = oi; }
    }
    if (lane == 0) {
        g_idx[p] = bi;
        atomicAdd(&g_hist[bi], 1);
    }
}

// ---------------------------------------------------------------------------
// K3: gather latents, quantization-loss partial, expand D->C, write out.
// (exact round-12 version)
// ---------------------------------------------------------------------------
__global__ __launch_bounds__(256) void k_output(const float* __restrict__ ew,
                                                const float* __restrict__ eb,
                                                float* __restrict__ out) {
    __shared__ float lat_s[32][33];
    __shared__ float exp_s[64][32];
    __shared__ float red[256];

    int bh  = blockIdx.x;
    int b   = bh >> 5, h = bh & 31;
    int tid = threadIdx.x;
    int pbase = bh * 32;

    float lsum = 0.f;
    for (int i = tid; i < 1024; i += 256) {
        int ww = i >> 5, d = i & 31;
        int ix = g_idx[pbase + ww];
        float lv = g_e[(size_t)ix * Dd + d];
        lat_s[ww][d] = lv;
        float dz = g_z[((size_t)pbase + ww) * Dd + d] - lv;
        lsum += dz * dz;
    }
    red[tid] = lsum;
    __syncthreads();
    for (int s = 128; s; s >>= 1) {
        if (tid < s) red[tid] += red[tid + s];
        __syncthreads();
    }
    if (tid == 0) g_loss_part[bh] = red[0];

    int w   = tid & 31;
    int cg8 = tid >> 5;

    float latr[32];
    #pragma unroll
    for (int d = 0; d < 32; d++) latr[d] = lat_s[w][d];

    for (int c0 = 0; c0 < Cc; c0 += 64) {
        __syncthreads();
        #pragma unroll
        for (int k = 0; k < 2; k++) {
            int i = tid + 256 * k;           // 0..511
            int cl = i >> 3, v = i & 7;
            *(float4*)&exp_s[cl][v * 4] =
                *(const float4*)(ew + (size_t)(c0 + cl) * Dd + v * 4);
        }
        __syncthreads();
        #pragma unroll
        for (int jj = 0; jj < 8; jj++) {
            int cl = cg8 + 8 * jj;
            int c  = c0 + cl;
            float s = eb[c];
            #pragma unroll
            for (int d4 = 0; d4 < 8; d4++) {
                float4 e4 = *(const float4*)&exp_s[cl][d4 * 4];
                s += e4.x * latr[4*d4] + e4.y * latr[4*d4+1]
                   + e4.z * latr[4*d4+2] + e4.w * latr[4*d4+3];
            }
            out[(((size_t)b * Cc + c) * Hh + h) * Ww + w] = s;
        }
    }
}

// ---------------------------------------------------------------------------
// K4: final scalars — loss mean and perplexity. (exact round-12 version)
// ---------------------------------------------------------------------------
__global__ void k_scalars(float* __restrict__ out, int osz) {
    __shared__ float red[256];
    int tid = threadIdx.x;

    float s = 0.f;
    for (int i = tid; i < 512; i += 256) s += g_loss_part[i];
    red[tid] = s;
    __syncthreads();
    for (int st = 128; st; st >>= 1) {
        if (tid < st) red[tid] += red[tid + st];
        __syncthreads();
    }
    if (tid == 0) out[osz - 2] = red[0] / (float)(Pp * Dd);
    __syncthreads();

    float e = 0.f;
    const float inv = 1.0f / (float)Pp;
    for (int i = tid; i < Nn; i += 256) {
        int c = g_hist[i];
        if (c > 0) {
            float u = (float)c * inv;
            e -= u * logf(u + 1e-6f);
        }
    }
    red[tid] = e;
    __syncthreads();
    for (int st = 128; st; st >>= 1) {
        if (tid < st) red[tid] += red[tid + st];
        __syncthreads();
    }
    if (tid == 0) out[osz - 1] = expf(red[0]);
}

// ---------------------------------------------------------------------------
extern "C" void kernel_launch(void* const* d_in, const int* in_sizes, int n_in,
                              void* d_out, int out_size) {
    const float* enc = (const float*)d_in[0];   // encodings [B,C,H,W]
    const float* emb = (const float*)d_in[1];   // emb_weight [N,D]
    const float* pw  = (const float*)d_in[2];   // proj_w [D,C]
    const float* pb  = (const float*)d_in[3];   // proj_b [D]
    const float* ew  = (const float*)d_in[4];   // exp_w [C,D]
    const float* eb  = (const float*)d_in[5];   // exp_b [C]
    float* out = (float*)d_out;

    cudaFuncSetAttribute(k_sims, cudaFuncAttributeMaxDynamicSharedMemorySize, SIMS_SMEM);

    k_zero_hist<<<Nn / 256, 256>>>();
    k_prep_e<<<Nn / 8, 256>>>(emb);
    k_project<<<Bb * Hh, 256>>>(enc, pw, pb);
    k_sims<<<Pp / 64, 256, SIMS_SMEM>>>();
    k_pass2<<<Pp / 8, 256>>>();
    k_output<<<Bb * Hh, 256>>>(ew, eb, out);
    k_scalars<<<1, 256>>>(out, out_size);
}

// round 16
// speedup vs baseline: 1.4588x; 1.0809x over previous
#include <cuda_runtime.h>
#include <cuda_fp16.h>
#include <math.h>
#include <cstdint>

#define Bb 16
#define Cc 512
#define Hh 32
#define Ww 32
#define Nn 16384
#define Dd 32
#define Pp 16384   // Bb*Hh*Ww

// ---------------------------------------------------------------------------
// Scratch (__device__ globals; no allocation allowed)
// ---------------------------------------------------------------------------
__device__ float g_z[Pp * Dd];        // normalized projected latents [p][d]
__device__ float g_e[Nn * Dd];        // normalized codebook fp32 [n][d] (rows 128B aligned)
__device__ uint4 g_eb[Nn * 4];        // codebook fp16: [n][32 half] = 64 B/row
__device__ float g_tmax[(size_t)Pp * 512];  // per-position per-32-code-entry max (fp16 sims)
__device__ int   g_idx[Pp];
__device__ int   g_hist[Nn];
__device__ float g_loss_part[512];

// ---------------------------------------------------------------------------
// PTX helpers (baseline PTX only: no 'a'-features)
// ---------------------------------------------------------------------------
__device__ __forceinline__ uint32_t smem_u32(const void* p) {
    uint32_t a;
    asm("{ .reg .u64 t; cvta.to.shared.u64 t, %1; cvt.u32.u64 %0, t; }" : "=r"(a) : "l"(p));
    return a;
}
__device__ __forceinline__ void ldsm4(uint32_t* r, uint32_t addr) {
    asm volatile("ldmatrix.sync.aligned.m8n8.x4.shared.b16 {%0,%1,%2,%3}, [%4];"
                 : "=r"(r[0]), "=r"(r[1]), "=r"(r[2]), "=r"(r[3]) : "r"(addr));
}
__device__ __forceinline__ void mma16816(float* d, const uint32_t* a, const uint32_t* b) {
    asm volatile("mma.sync.aligned.m16n8k16.row.col.f32.f16.f16.f32 "
                 "{%0,%1,%2,%3}, {%4,%5,%6,%7}, {%8,%9}, {%0,%1,%2,%3};"
                 : "+f"(d[0]), "+f"(d[1]), "+f"(d[2]), "+f"(d[3])
                 : "r"(a[0]), "r"(a[1]), "r"(a[2]), "r"(a[3]), "r"(b[0]), "r"(b[1]));
}
__device__ __forceinline__ void cpasync16(uint32_t dst, const void* src) {
    asm volatile("cp.async.cg.shared.global [%0], [%1], 16;" :: "r"(dst), "l"(src));
}
#define CP_COMMIT() asm volatile("cp.async.commit_group;" ::: "memory")
#define CP_WAIT0()  asm volatile("cp.async.wait_group 0;" ::: "memory")
#define CP_WAIT1()  asm volatile("cp.async.wait_group 1;" ::: "memory")

__device__ __forceinline__ bool better(float xv, int xi, float yv, int yi) {
    return xv > yv || (xv == yv && xi < yi);
}

// ---------------------------------------------------------------------------
// K_zero: clear histogram (keeps k_sims in the ncu capture slot)
// ---------------------------------------------------------------------------
__global__ void k_zero_hist() {
    g_hist[blockIdx.x * 256 + threadIdx.x] = 0;
}

// ---------------------------------------------------------------------------
// K_prep_e: normalize codebook rows; fp32 copy + single fp16 copy.
// ---------------------------------------------------------------------------
__global__ void k_prep_e(const float* __restrict__ emb) {
    int warp = threadIdx.x >> 5, lane = threadIdx.x & 31;
    int n = blockIdx.x * 8 + warp;
    float v = emb[n * Dd + lane];
    float ss = v * v;
    #pragma unroll
    for (int o = 16; o; o >>= 1) ss += __shfl_xor_sync(0xffffffffu, ss, o);
    float rn = 1.0f / fmaxf(sqrtf(ss), 1e-6f);
    float zn = v * rn;
    g_e[n * Dd + lane] = zn;
    ((__half*)g_eb)[(size_t)n * 32 + lane] = __float2half(zn);
}

// ---------------------------------------------------------------------------
// K1: projection (1x1 conv C->D) + L2 normalize along D.
// ---------------------------------------------------------------------------
__global__ __launch_bounds__(256) void k_project(const float* __restrict__ enc,
                                                 const float* __restrict__ pw,
                                                 const float* __restrict__ pb) {
    __shared__ float enc_s[64][32];
    __shared__ float proj_s[32][64];
    __shared__ float z_s[32][33];
    __shared__ float rn_s[32];

    int bh  = blockIdx.x;
    int tid = threadIdx.x;
    int w   = tid & 31;
    int dg  = tid >> 5;

    const float* encbase = enc + (size_t)(bh >> 5) * Cc * Hh * Ww + (size_t)(bh & 31) * Ww;

    float acc[4] = {0.f, 0.f, 0.f, 0.f};

    for (int c0 = 0; c0 < Cc; c0 += 64) {
        #pragma unroll
        for (int k = 0; k < 2; k++) {
            int i = tid + 256 * k;            // 0..511
            int cl = i >> 3, v = i & 7;
            *(float4*)&enc_s[cl][v * 4] =
                *(const float4*)(encbase + (size_t)(c0 + cl) * (Hh * Ww) + v * 4);
        }
        #pragma unroll
        for (int k = 0; k < 2; k++) {
            int i = tid + 256 * k;
            int d = i >> 4, c4 = i & 15;
            *(float4*)&proj_s[d][c4 * 4] =
                *(const float4*)(pw + d * Cc + c0 + c4 * 4);
        }
        __syncthreads();
        #pragma unroll 16
        for (int cl = 0; cl < 64; cl++) {
            float ev = enc_s[cl][w];
            #pragma unroll
            for (int j = 0; j < 4; j++) acc[j] += proj_s[dg + 8 * j][cl] * ev;
        }
        __syncthreads();
    }
    #pragma unroll
    for (int j = 0; j < 4; j++) z_s[dg + 8 * j][w] = acc[j] + pb[dg + 8 * j];
    __syncthreads();

    if (tid < 32) {
        float ss = 0.f;
        #pragma unroll
        for (int d = 0; d < 32; d++) { float v = z_s[d][tid]; ss += v * v; }
        rn_s[tid] = 1.0f / fmaxf(sqrtf(ss), 1e-6f);
    }
    __syncthreads();

    for (int i = tid; i < 1024; i += 256) {
        int ww = i >> 5, d = i & 31;
        g_z[((size_t)bh * 32 + ww) * Dd + d] = z_s[d][ww] * rn_s[ww];
    }
}

// ---------------------------------------------------------------------------
// K2: single-term fp16 HMMA sims (K=32); per-position per-32-code-entry MAX.
// Software-pipelined epilogue: tile t's entry-max reduction executes AFTER
// tile t+1's MMA issues (epilogue is register/shfl/gmem only), filling the
// LDSM/tensor wait window instead of extending the per-tile critical path.
// Two static accumulator banks (accA/accB), manual 2x unroll.
// ---------------------------------------------------------------------------
#define A_BYTES   5120                        // 64 * 80
#define B_BYTES   10240                       // 128 * 80
#define SIMS_SMEM (A_BYTES + 3 * B_BYTES)     // 35840

__global__ __launch_bounds__(256, 2) void k_sims() {
    extern __shared__ __align__(16) char sm[];
    __half* As = (__half*)sm;                 // stride 40 half = 80 B
    uint32_t sbase = smem_u32(sm);

    int tid  = threadIdx.x;
    int lane = tid & 31;
    int w    = tid >> 5;      // 0..7
    int rg   = w & 3;         // row group (16 positions)
    int nh   = w >> 2;        // n-half (64 codes)
    int tg   = lane & 3;
    int gr   = lane >> 2;     // row-in-group 0..7
    int pbase = blockIdx.x * 64;

    for (int i = tid; i < 64 * 32; i += 256) {
        int row = i >> 5, d = i & 31;
        As[row * 40 + d] = __float2half(g_z[(size_t)(pbase + row) * Dd + d]);
    }

    uint32_t cprow = (uint32_t)(tid >> 1);
    uint32_t cphalf = (uint32_t)((tid & 1) * 32);
    uint32_t srcBase = cprow * 64 + cphalf;
    uint32_t dstBase = cprow * 80 + cphalf;

    const char* ebase = (const char*)g_eb;
    #pragma unroll
    for (int j = 0; j < 2; j++)
        cpasync16(sbase + A_BYTES + dstBase + j * 16, ebase + srcBase + j * 16);
    CP_COMMIT();
    #pragma unroll
    for (int j = 0; j < 2; j++)
        cpasync16(sbase + A_BYTES + B_BYTES + dstBase + j * 16,
                  ebase + 8192 + srcBase + j * 16);
    CP_COMMIT();
    __syncthreads();

    uint32_t afr[2][4];
    int q = lane >> 3, r = lane & 7;
    {
        uint32_t abase = sbase + (uint32_t)((rg * 16 + (q & 1) * 8 + r) * 80
                                            + (q >> 1) * 16);
        #pragma unroll
        for (int kk = 0; kk < 2; kk++) ldsm4(afr[kk], abase + kk * 32);
    }
    uint32_t brow_off = (uint32_t)((nh * 64 + (q >> 1) * 8 + r) * 80 + (q & 1) * 16);

    float accA[8][4], accB[8][4];

    // per-tile sync + prefetch + MMA into the given bank
    #define DO_TILE(ACC, T) do {                                                   \
        if ((T) < 126) CP_WAIT1(); else CP_WAIT0();                                \
        __syncthreads();                                                           \
        if ((T) + 2 < 128) {                                                       \
            const char* _src = ebase + (size_t)((T) + 2) * 8192 + srcBase;         \
            uint32_t _dst = sbase + A_BYTES                                        \
                          + (uint32_t)((((T) + 2) % 3) * B_BYTES) + dstBase;       \
            cpasync16(_dst, _src);                                                 \
            cpasync16(_dst + 16, _src + 16);                                       \
            CP_COMMIT();                                                           \
        }                                                                          \
        uint32_t _bb = sbase + A_BYTES + (uint32_t)(((T) % 3) * B_BYTES) + brow_off;\
        _Pragma("unroll")                                                          \
        for (int _nb = 0; _nb < 8; _nb++)                                          \
            _Pragma("unroll")                                                      \
            for (int _i = 0; _i < 4; _i++) ACC[_nb][_i] = 0.f;                     \
        _Pragma("unroll")                                                          \
        for (int _j = 0; _j < 4; _j++) {                                           \
            uint32_t _bbj = _bb + (uint32_t)_j * (16 * 80);                        \
            uint32_t _b0[4], _b1[4];                                               \
            ldsm4(_b0, _bbj);                                                      \
            ldsm4(_b1, _bbj + 32);                                                 \
            mma16816(ACC[2*_j],   afr[0], _b0);                                    \
            mma16816(ACC[2*_j+1], afr[0], _b0 + 2);                                \
            mma16816(ACC[2*_j],   afr[1], _b1);                                    \
            mma16816(ACC[2*_j+1], afr[1], _b1 + 2);                                \
        }                                                                          \
    } while (0)

    // entry-max reduction + store for the given bank / tile index
    #define EPILOGUE(ACC, T) do {                                                  \
        float mA0, mA1, mB0, mB1;                                                  \
        {                                                                          \
            float a0 = fmaxf(fmaxf(ACC[0][0], ACC[0][1]), fmaxf(ACC[1][0], ACC[1][1])); \
            float a1 = fmaxf(fmaxf(ACC[2][0], ACC[2][1]), fmaxf(ACC[3][0], ACC[3][1])); \
            mA0 = fmaxf(a0, a1);                                                   \
            float a2 = fmaxf(fmaxf(ACC[4][0], ACC[4][1]), fmaxf(ACC[5][0], ACC[5][1])); \
            float a3 = fmaxf(fmaxf(ACC[6][0], ACC[6][1]), fmaxf(ACC[7][0], ACC[7][1])); \
            mA1 = fmaxf(a2, a3);                                                   \
            float b0 = fmaxf(fmaxf(ACC[0][2], ACC[0][3]), fmaxf(ACC[1][2], ACC[1][3])); \
            float b1 = fmaxf(fmaxf(ACC[2][2], ACC[2][3]), fmaxf(ACC[3][2], ACC[3][3])); \
            mB0 = fmaxf(b0, b1);                                                   \
            float b2 = fmaxf(fmaxf(ACC[4][2], ACC[4][3]), fmaxf(ACC[5][2], ACC[5][3])); \
            float b3 = fmaxf(fmaxf(ACC[6][2], ACC[6][3]), fmaxf(ACC[7][2], ACC[7][3])); \
            mB1 = fmaxf(b2, b3);                                                   \
        }                                                                          \
        mA0 = fmaxf(mA0, __shfl_xor_sync(0xffffffffu, mA0, 1));                    \
        mA0 = fmaxf(mA0, __shfl_xor_sync(0xffffffffu, mA0, 2));                    \
        mA1 = fmaxf(mA1, __shfl_xor_sync(0xffffffffu, mA1, 1));                    \
        mA1 = fmaxf(mA1, __shfl_xor_sync(0xffffffffu, mA1, 2));                    \
        mB0 = fmaxf(mB0, __shfl_xor_sync(0xffffffffu, mB0, 1));                    \
        mB0 = fmaxf(mB0, __shfl_xor_sync(0xffffffffu, mB0, 2));                    \
        mB1 = fmaxf(mB1, __shfl_xor_sync(0xffffffffu, mB1, 1));                    \
        mB1 = fmaxf(mB1, __shfl_xor_sync(0xffffffffu, mB1, 2));                    \
        if (tg == 0) {                                                             \
            int _posA = rg * 16 + gr;                                              \
            size_t _ba = (size_t)(pbase + _posA) * 512 + (T) * 4 + nh * 2;         \
            *(float2*)&g_tmax[_ba] = make_float2(mA0, mA1);                        \
            size_t _bbx = _ba + (size_t)8 * 512;                                   \
            *(float2*)&g_tmax[_bbx] = make_float2(mB0, mB1);                       \
        }                                                                          \
    } while (0)

    // tile 0 (prologue of the pipeline)
    DO_TILE(accA, 0);
    for (int t2 = 1; t2 < 127; t2 += 2) {
        DO_TILE(accB, t2);        // tile t2 MMAs issue...
        EPILOGUE(accA, t2 - 1);   // ...then prior tile's epilogue fills the wait
        DO_TILE(accA, t2 + 1);
        EPILOGUE(accB, t2);
    }
    DO_TILE(accB, 127);
    EPILOGUE(accA, 126);
    EPILOGUE(accB, 127);

    #undef DO_TILE
    #undef EPILOGUE
}

// ---------------------------------------------------------------------------
// K_pass2: adaptive exact rescore (measured 26.1 us).
// fp16 sim error eps <= ~1e-3; rescore every entry with approx-max
// >= v1 - 3e-3 (provably contains every code that could beat v1).
// ---------------------------------------------------------------------------
__global__ __launch_bounds__(256) void k_pass2() {
    __shared__ float zs[8][32];
    int tid  = threadIdx.x;
    int wp   = tid >> 5;
    int lane = tid & 31;
    int p    = blockIdx.x * 8 + wp;

    zs[wp][lane] = g_z[(size_t)p * Dd + lane];
    __syncwarp();

    const float4* tm = (const float4*)(g_tmax + (size_t)p * 512 + lane * 16);
    float ev[16];
    float v1 = -3e38f;
    #pragma unroll
    for (int qq = 0; qq < 4; qq++) {
        float4 f = tm[qq];
        ev[qq * 4 + 0] = f.x; ev[qq * 4 + 1] = f.y;
        ev[qq * 4 + 2] = f.z; ev[qq * 4 + 3] = f.w;
        v1 = fmaxf(v1, fmaxf(fmaxf(f.x, f.y), fmaxf(f.z, f.w)));
    }
    #pragma unroll
    for (int o = 16; o; o >>= 1) v1 = fmaxf(v1, __shfl_xor_sync(0xffffffffu, v1, o));

    float thr = v1 - 3e-3f;
    uint32_t mymask = 0;
    #pragma unroll
    for (int j = 0; j < 16; j++)
        if (ev[j] >= thr) mymask |= (1u << j);

    int cg = lane >> 2, qt = lane & 3;
    float zq[8];
    #pragma unroll
    for (int j = 0; j < 8; j++) zq[j] = zs[wp][qt * 8 + j];

    float bv = -3e38f;
    int   bi = 0x7fffffff;
    for (;;) {
        uint32_t act = __ballot_sync(0xffffffffu, mymask != 0);
        if (!act) break;
        int src = __ffs(act) - 1;
        uint32_t m = __shfl_sync(0xffffffffu, mymask, src);
        int j = __ffs(m) - 1;
        if (lane == src) mymask &= mymask - 1;
        int e = src * 16 + j;
        #pragma unroll
        for (int it = 0; it < 4; it++) {
            int c = e * 32 + it * 8 + cg;
            const float4* er = (const float4*)(g_e + (size_t)c * Dd + qt * 8);
            float4 a = er[0], b = er[1];
            float s = a.x * zq[0] + a.y * zq[1] + a.z * zq[2] + a.w * zq[3]
                    + b.x * zq[4] + b.y * zq[5] + b.z * zq[6] + b.w * zq[7];
            s += __shfl_xor_sync(0xffffffffu, s, 1);
            s += __shfl_xor_sync(0xffffffffu, s, 2);
            if (better(s, c, bv, bi)) { bv = s; bi = c; }
        }
    }
    #pragma unroll
    for (int o = 16; o >= 4; o >>= 1) {
        float ov = __shfl_xor_sync(0xffffffffu, bv, o);
        int   oi = __shfl_xor_sync(0xffffffffu, bi, o);
        if (better(ov, oi, bv, bi)) { bv = ov; bi = oi; }
    }
    if (lane == 0) {
        g_idx[p] = bi;
        atomicAdd(&g_hist[bi], 1);
    }
}

// ---------------------------------------------------------------------------
// K3: gather latents, quantization-loss partial, expand D->C, write out.
// ---------------------------------------------------------------------------
__global__ __launch_bounds__(256) void k_output(const float* __restrict__ ew,
                                                const float* __restrict__ eb,
                                                float* __restrict__ out) {
    __shared__ float lat_s[32][33];
    __shared__ float exp_s[64][32];
    __shared__ float red[256];

    int bh  = blockIdx.x;
    int b   = bh >> 5, h = bh & 31;
    int tid = threadIdx.x;
    int pbase = bh * 32;

    float lsum = 0.f;
    for (int i = tid; i < 1024; i += 256) {
        int ww = i >> 5, d = i & 31;
        int ix = g_idx[pbase + ww];
        float lv = g_e[(size_t)ix * Dd + d];
        lat_s[ww][d] = lv;
        float dz = g_z[((size_t)pbase + ww) * Dd + d] - lv;
        lsum += dz * dz;
    }
    red[tid] = lsum;
    __syncthreads();
    for (int s = 128; s; s >>= 1) {
        if (tid < s) red[tid] += red[tid + s];
        __syncthreads();
    }
    if (tid == 0) g_loss_part[bh] = red[0];

    int w   = tid & 31;
    int cg8 = tid >> 5;

    float latr[32];
    #pragma unroll
    for (int d = 0; d < 32; d++) latr[d] = lat_s[w][d];

    for (int c0 = 0; c0 < Cc; c0 += 64) {
        __syncthreads();
        #pragma unroll
        for (int k = 0; k < 2; k++) {
            int i = tid + 256 * k;           // 0..511
            int cl = i >> 3, v = i & 7;
            *(float4*)&exp_s[cl][v * 4] =
                *(const float4*)(ew + (size_t)(c0 + cl) * Dd + v * 4);
        }
        __syncthreads();
        #pragma unroll
        for (int jj = 0; jj < 8; jj++) {
            int cl = cg8 + 8 * jj;
            int c  = c0 + cl;
            float s = eb[c];
            #pragma unroll
            for (int d4 = 0; d4 < 8; d4++) {
                float4 e4 = *(const float4*)&exp_s[cl][d4 * 4];
                s += e4.x * latr[4*d4] + e4.y * latr[4*d4+1]
                   + e4.z * latr[4*d4+2] + e4.w * latr[4*d4+3];
            }
            out[(((size_t)b * Cc + c) * Hh + h) * Ww + w] = s;
        }
    }
}

// ---------------------------------------------------------------------------
// K4: final scalars — loss mean and perplexity.
// ---------------------------------------------------------------------------
__global__ void k_scalars(float* __restrict__ out, int osz) {
    __shared__ float red[256];
    int tid = threadIdx.x;

    float s = 0.f;
    for (int i = tid; i < 512; i += 256) s += g_loss_part[i];
    red[tid] = s;
    __syncthreads();
    for (int st = 128; st; st >>= 1) {
        if (tid < st) red[tid] += red[tid + st];
        __syncthreads();
    }
    if (tid == 0) out[osz - 2] = red[0] / (float)(Pp * Dd);
    __syncthreads();

    float e = 0.f;
    const float inv = 1.0f / (float)Pp;
    for (int i = tid; i < Nn; i += 256) {
        int c = g_hist[i];
        if (c > 0) {
            float u = (float)c * inv;
            e -= u * logf(u + 1e-6f);
        }
    }
    red[tid] = e;
    __syncthreads();
    for (int st = 128; st; st >>= 1) {
        if (tid < st) red[tid] += red[tid + st];
        __syncthreads();
    }
    if (tid == 0) out[osz - 1] = expf(red[0]);
}

// ---------------------------------------------------------------------------
extern "C" void kernel_launch(void* const* d_in, const int* in_sizes, int n_in,
                              void* d_out, int out_size) {
    const float* enc = (const float*)d_in[0];   // encodings [B,C,H,W]
    const float* emb = (const float*)d_in[1];   // emb_weight [N,D]
    const float* pw  = (const float*)d_in[2];   // proj_w [D,C]
    const float* pb  = (const float*)d_in[3];   // proj_b [D]
    const float* ew  = (const float*)d_in[4];   // exp_w [C,D]
    const float* eb  = (const float*)d_in[5];   // exp_b [C]
    float* out = (float*)d_out;

    cudaFuncSetAttribute(k_sims, cudaFuncAttributeMaxDynamicSharedMemorySize, SIMS_SMEM);

    k_zero_hist<<<Nn / 256, 256>>>();
    k_prep_e<<<Nn / 8, 256>>>(emb);
    k_project<<<Bb * Hh, 256>>>(enc, pw, pb);
    k_sims<<<Pp / 64, 256, SIMS_SMEM>>>();
    k_pass2<<<Pp / 8, 256>>>();
    k_output<<<Bb * Hh, 256>>>(ew, eb, out);
    k_scalars<<<1, 256>>>(out, out_size);
}

// round 17
// speedup vs baseline: 1.5567x; 1.0671x over previous
#include <cuda_runtime.h>
#include <cuda_fp16.h>
#include <math.h>
#include <cstdint>

#define Bb 16
#define Cc 512
#define Hh 32
#define Ww 32
#define Nn 16384
#define Dd 32
#define Pp 16384   // Bb*Hh*Ww

// ---------------------------------------------------------------------------
// Scratch (__device__ globals; no allocation allowed)
// ---------------------------------------------------------------------------
__device__ float  g_z[Pp * Dd];        // normalized projected latents [p][d]
__device__ float  g_e[Nn * Dd];        // normalized codebook fp32 [n][d]
__device__ uint4  g_eb[Nn * 4];        // codebook fp16: [n][32 half] = 64 B/row
__device__ __half g_tmaxh[(size_t)Pp * 512];  // per-position per-32-code-entry max (fp16)
__device__ int    g_idx[Pp];
__device__ int    g_hist[Nn];
__device__ float  g_loss_part[512];

// ---------------------------------------------------------------------------
// PTX helpers (baseline PTX only: no 'a'-features)
// ---------------------------------------------------------------------------
__device__ __forceinline__ uint32_t smem_u32(const void* p) {
    uint32_t a;
    asm("{ .reg .u64 t; cvta.to.shared.u64 t, %1; cvt.u32.u64 %0, t; }" : "=r"(a) : "l"(p));
    return a;
}
__device__ __forceinline__ void ldsm4(uint32_t* r, uint32_t addr) {
    asm volatile("ldmatrix.sync.aligned.m8n8.x4.shared.b16 {%0,%1,%2,%3}, [%4];"
                 : "=r"(r[0]), "=r"(r[1]), "=r"(r[2]), "=r"(r[3]) : "r"(addr));
}
__device__ __forceinline__ void mma16816(float* d, const uint32_t* a, const uint32_t* b) {
    asm volatile("mma.sync.aligned.m16n8k16.row.col.f32.f16.f16.f32 "
                 "{%0,%1,%2,%3}, {%4,%5,%6,%7}, {%8,%9}, {%0,%1,%2,%3};"
                 : "+f"(d[0]), "+f"(d[1]), "+f"(d[2]), "+f"(d[3])
                 : "r"(a[0]), "r"(a[1]), "r"(a[2]), "r"(a[3]), "r"(b[0]), "r"(b[1]));
}
__device__ __forceinline__ void cpasync16(uint32_t dst, const void* src) {
    asm volatile("cp.async.cg.shared.global [%0], [%1], 16;" :: "r"(dst), "l"(src));
}
#define CP_COMMIT() asm volatile("cp.async.commit_group;" ::: "memory")
#define CP_WAIT0()  asm volatile("cp.async.wait_group 0;" ::: "memory")
#define CP_WAIT1()  asm volatile("cp.async.wait_group 1;" ::: "memory")

__device__ __forceinline__ bool better(float xv, int xi, float yv, int yi) {
    return xv > yv || (xv == yv && xi < yi);
}

// ---------------------------------------------------------------------------
// K_prep_e: normalize codebook rows; fp32 copy + fp16 copy; zero hist slots.
// ---------------------------------------------------------------------------
__global__ void k_prep_e(const float* __restrict__ emb) {
    int warp = threadIdx.x >> 5, lane = threadIdx.x & 31;
    if (threadIdx.x < 8) g_hist[blockIdx.x * 8 + threadIdx.x] = 0;
    int n = blockIdx.x * 8 + warp;
    float v = emb[n * Dd + lane];
    float ss = v * v;
    #pragma unroll
    for (int o = 16; o; o >>= 1) ss += __shfl_xor_sync(0xffffffffu, ss, o);
    float rn = 1.0f / fmaxf(sqrtf(ss), 1e-6f);
    float zn = v * rn;
    g_e[n * Dd + lane] = zn;
    ((__half*)g_eb)[(size_t)n * 32 + lane] = __float2half(zn);
}

// ---------------------------------------------------------------------------
// K1: projection (1x1 conv C->D) + L2 normalize along D.
// ---------------------------------------------------------------------------
__global__ __launch_bounds__(256) void k_project(const float* __restrict__ enc,
                                                 const float* __restrict__ pw,
                                                 const float* __restrict__ pb) {
    __shared__ float enc_s[64][32];
    __shared__ float proj_s[32][64];
    __shared__ float z_s[32][33];
    __shared__ float rn_s[32];

    int bh  = blockIdx.x;
    int tid = threadIdx.x;
    int w   = tid & 31;
    int dg  = tid >> 5;

    const float* encbase = enc + (size_t)(bh >> 5) * Cc * Hh * Ww + (size_t)(bh & 31) * Ww;

    float acc[4] = {0.f, 0.f, 0.f, 0.f};

    for (int c0 = 0; c0 < Cc; c0 += 64) {
        #pragma unroll
        for (int k = 0; k < 2; k++) {
            int i = tid + 256 * k;            // 0..511
            int cl = i >> 3, v = i & 7;
            *(float4*)&enc_s[cl][v * 4] =
                *(const float4*)(encbase + (size_t)(c0 + cl) * (Hh * Ww) + v * 4);
        }
        #pragma unroll
        for (int k = 0; k < 2; k++) {
            int i = tid + 256 * k;
            int d = i >> 4, c4 = i & 15;
            *(float4*)&proj_s[d][c4 * 4] =
                *(const float4*)(pw + d * Cc + c0 + c4 * 4);
        }
        __syncthreads();
        #pragma unroll 16
        for (int cl = 0; cl < 64; cl++) {
            float ev = enc_s[cl][w];
            #pragma unroll
            for (int j = 0; j < 4; j++) acc[j] += proj_s[dg + 8 * j][cl] * ev;
        }
        __syncthreads();
    }
    #pragma unroll
    for (int j = 0; j < 4; j++) z_s[dg + 8 * j][w] = acc[j] + pb[dg + 8 * j];
    __syncthreads();

    if (tid < 32) {
        float ss = 0.f;
        #pragma unroll
        for (int d = 0; d < 32; d++) { float v = z_s[d][tid]; ss += v * v; }
        rn_s[tid] = 1.0f / fmaxf(sqrtf(ss), 1e-6f);
    }
    __syncthreads();

    for (int i = tid; i < 1024; i += 256) {
        int ww = i >> 5, d = i & 31;
        g_z[((size_t)bh * 32 + ww) * Dd + d] = z_s[d][ww] * rn_s[ww];
    }
}

// ---------------------------------------------------------------------------
// K2: single-term fp16 HMMA sims (K=32); per-position per-32-code-entry MAX
// stored as fp16. Software-pipelined epilogue (round-16 structure).
// ---------------------------------------------------------------------------
#define A_BYTES   5120                        // 64 * 80
#define B_BYTES   10240                       // 128 * 80
#define SIMS_SMEM (A_BYTES + 3 * B_BYTES)     // 35840

__global__ __launch_bounds__(256, 2) void k_sims() {
    extern __shared__ __align__(16) char sm[];
    __half* As = (__half*)sm;                 // stride 40 half = 80 B
    uint32_t sbase = smem_u32(sm);

    int tid  = threadIdx.x;
    int lane = tid & 31;
    int w    = tid >> 5;      // 0..7
    int rg   = w & 3;         // row group (16 positions)
    int nh   = w >> 2;        // n-half (64 codes)
    int tg   = lane & 3;
    int gr   = lane >> 2;     // row-in-group 0..7
    int pbase = blockIdx.x * 64;

    for (int i = tid; i < 64 * 32; i += 256) {
        int row = i >> 5, d = i & 31;
        As[row * 40 + d] = __float2half(g_z[(size_t)(pbase + row) * Dd + d]);
    }

    uint32_t cprow = (uint32_t)(tid >> 1);
    uint32_t cphalf = (uint32_t)((tid & 1) * 32);
    uint32_t srcBase = cprow * 64 + cphalf;
    uint32_t dstBase = cprow * 80 + cphalf;

    const char* ebase = (const char*)g_eb;
    #pragma unroll
    for (int j = 0; j < 2; j++)
        cpasync16(sbase + A_BYTES + dstBase + j * 16, ebase + srcBase + j * 16);
    CP_COMMIT();
    #pragma unroll
    for (int j = 0; j < 2; j++)
        cpasync16(sbase + A_BYTES + B_BYTES + dstBase + j * 16,
                  ebase + 8192 + srcBase + j * 16);
    CP_COMMIT();
    __syncthreads();

    uint32_t afr[2][4];
    int q = lane >> 3, r = lane & 7;
    {
        uint32_t abase = sbase + (uint32_t)((rg * 16 + (q & 1) * 8 + r) * 80
                                            + (q >> 1) * 16);
        #pragma unroll
        for (int kk = 0; kk < 2; kk++) ldsm4(afr[kk], abase + kk * 32);
    }
    uint32_t brow_off = (uint32_t)((nh * 64 + (q >> 1) * 8 + r) * 80 + (q & 1) * 16);

    float accA[8][4], accB[8][4];

    #define DO_TILE(ACC, T) do {                                                   \
        if ((T) < 126) CP_WAIT1(); else CP_WAIT0();                                \
        __syncthreads();                                                           \
        if ((T) + 2 < 128) {                                                       \
            const char* _src = ebase + (size_t)((T) + 2) * 8192 + srcBase;         \
            uint32_t _dst = sbase + A_BYTES                                        \
                          + (uint32_t)((((T) + 2) % 3) * B_BYTES) + dstBase;       \
            cpasync16(_dst, _src);                                                 \
            cpasync16(_dst + 16, _src + 16);                                       \
            CP_COMMIT();                                                           \
        }                                                                          \
        uint32_t _bb = sbase + A_BYTES + (uint32_t)(((T) % 3) * B_BYTES) + brow_off;\
        _Pragma("unroll")                                                          \
        for (int _nb = 0; _nb < 8; _nb++)                                          \
            _Pragma("unroll")                                                      \
            for (int _i = 0; _i < 4; _i++) ACC[_nb][_i] = 0.f;                     \
        _Pragma("unroll")                                                          \
        for (int _j = 0; _j < 4; _j++) {                                           \
            uint32_t _bbj = _bb + (uint32_t)_j * (16 * 80);                        \
            uint32_t _b0[4], _b1[4];                                               \
            ldsm4(_b0, _bbj);                                                      \
            ldsm4(_b1, _bbj + 32);                                                 \
            mma16816(ACC[2*_j],   afr[0], _b0);                                    \
            mma16816(ACC[2*_j+1], afr[0], _b0 + 2);                                \
            mma16816(ACC[2*_j],   afr[1], _b1);                                    \
            mma16816(ACC[2*_j+1], afr[1], _b1 + 2);                                \
        }                                                                          \
    } while (0)

    #define EPILOGUE(ACC, T) do {                                                  \
        float mA0, mA1, mB0, mB1;                                                  \
        {                                                                          \
            float a0 = fmaxf(fmaxf(ACC[0][0], ACC[0][1]), fmaxf(ACC[1][0], ACC[1][1])); \
            float a1 = fmaxf(fmaxf(ACC[2][0], ACC[2][1]), fmaxf(ACC[3][0], ACC[3][1])); \
            mA0 = fmaxf(a0, a1);                                                   \
            float a2 = fmaxf(fmaxf(ACC[4][0], ACC[4][1]), fmaxf(ACC[5][0], ACC[5][1])); \
            float a3 = fmaxf(fmaxf(ACC[6][0], ACC[6][1]), fmaxf(ACC[7][0], ACC[7][1])); \
            mA1 = fmaxf(a2, a3);                                                   \
            float b0 = fmaxf(fmaxf(ACC[0][2], ACC[0][3]), fmaxf(ACC[1][2], ACC[1][3])); \
            float b1 = fmaxf(fmaxf(ACC[2][2], ACC[2][3]), fmaxf(ACC[3][2], ACC[3][3])); \
            mB0 = fmaxf(b0, b1);                                                   \
            float b2 = fmaxf(fmaxf(ACC[4][2], ACC[4][3]), fmaxf(ACC[5][2], ACC[5][3])); \
            float b3 = fmaxf(fmaxf(ACC[6][2], ACC[6][3]), fmaxf(ACC[7][2], ACC[7][3])); \
            mB1 = fmaxf(b2, b3);                                                   \
        }                                                                          \
        mA0 = fmaxf(mA0, __shfl_xor_sync(0xffffffffu, mA0, 1));                    \
        mA0 = fmaxf(mA0, __shfl_xor_sync(0xffffffffu, mA0, 2));                    \
        mA1 = fmaxf(mA1, __shfl_xor_sync(0xffffffffu, mA1, 1));                    \
        mA1 = fmaxf(mA1, __shfl_xor_sync(0xffffffffu, mA1, 2));                    \
        mB0 = fmaxf(mB0, __shfl_xor_sync(0xffffffffu, mB0, 1));                    \
        mB0 = fmaxf(mB0, __shfl_xor_sync(0xffffffffu, mB0, 2));                    \
        mB1 = fmaxf(mB1, __shfl_xor_sync(0xffffffffu, mB1, 1));                    \
        mB1 = fmaxf(mB1, __shfl_xor_sync(0xffffffffu, mB1, 2));                    \
        if (tg == 0) {                                                             \
            int _posA = rg * 16 + gr;                                              \
            size_t _ba = (size_t)(pbase + _posA) * 512 + (T) * 4 + nh * 2;         \
            *(__half2*)&g_tmaxh[_ba] = __float22half2_rn(make_float2(mA0, mA1));   \
            size_t _bbx = _ba + (size_t)8 * 512;                                   \
            *(__half2*)&g_tmaxh[_bbx] = __float22half2_rn(make_float2(mB0, mB1));  \
        }                                                                          \
    } while (0)

    DO_TILE(accA, 0);
    for (int t2 = 1; t2 < 127; t2 += 2) {
        DO_TILE(accB, t2);
        EPILOGUE(accA, t2 - 1);
        DO_TILE(accA, t2 + 1);
        EPILOGUE(accB, t2);
    }
    DO_TILE(accB, 127);
    EPILOGUE(accA, 126);
    EPILOGUE(accB, 127);

    #undef DO_TILE
    #undef EPILOGUE
}

// ---------------------------------------------------------------------------
// K_pass2: adaptive exact rescore over fp16 entry maxima.
// Widened threshold: fp16 sim error (~1e-3) + fp16 tmax rounding (2x ~5e-4)
// -> true winner's entry satisfies m_e >= v1 - 3e-3; use v1 - 4e-3.
// One warp per position; 8 positions per block.
// ---------------------------------------------------------------------------
__global__ __launch_bounds__(256) void k_pass2() {
    __shared__ float zs[8][32];
    int tid  = threadIdx.x;
    int wp   = tid >> 5;
    int lane = tid & 31;
    int p    = blockIdx.x * 8 + wp;

    zs[wp][lane] = g_z[(size_t)p * Dd + lane];
    __syncwarp();

    // ---- load this lane's 16 fp16 entry maxima (32 B = 2x uint4) ----
    const uint4* tm = (const uint4*)(g_tmaxh + (size_t)p * 512 + lane * 16);
    uint4 u0 = tm[0], u1 = tm[1];
    float ev[16];
    {
        uint32_t ws[8] = {u0.x, u0.y, u0.z, u0.w, u1.x, u1.y, u1.z, u1.w};
        #pragma unroll
        for (int j = 0; j < 8; j++) {
            float2 f = __half22float2(*(__half2*)&ws[j]);
            ev[2 * j] = f.x; ev[2 * j + 1] = f.y;
        }
    }
    float v1 = -3e38f;
    #pragma unroll
    for (int j = 0; j < 16; j++) v1 = fmaxf(v1, ev[j]);
    #pragma unroll
    for (int o = 16; o; o >>= 1) v1 = fmaxf(v1, __shfl_xor_sync(0xffffffffu, v1, o));

    // ---- qualifying-entry bitmask per lane ----
    float thr = v1 - 4e-3f;
    uint32_t mymask = 0;
    #pragma unroll
    for (int j = 0; j < 16; j++)
        if (ev[j] >= thr) mymask |= (1u << j);

    // ---- rescore loop: one entry (32 codes) per iteration ----
    int cg = lane >> 2, qt = lane & 3;
    float zq[8];
    #pragma unroll
    for (int j = 0; j < 8; j++) zq[j] = zs[wp][qt * 8 + j];

    float bv = -3e38f;
    int   bi = 0x7fffffff;
    for (;;) {
        uint32_t act = __ballot_sync(0xffffffffu, mymask != 0);
        if (!act) break;
        int src = __ffs(act) - 1;
        uint32_t m = __shfl_sync(0xffffffffu, mymask, src);
        int j = __ffs(m) - 1;
        if (lane == src) mymask &= mymask - 1;
        int e = src * 16 + j;
        #pragma unroll
        for (int it = 0; it < 4; it++) {
            int c = e * 32 + it * 8 + cg;
            const float4* er = (const float4*)(g_e + (size_t)c * Dd + qt * 8);
            float4 a = er[0], b = er[1];
            float s = a.x * zq[0] + a.y * zq[1] + a.z * zq[2] + a.w * zq[3]
                    + b.x * zq[4] + b.y * zq[5] + b.z * zq[6] + b.w * zq[7];
            s += __shfl_xor_sync(0xffffffffu, s, 1);
            s += __shfl_xor_sync(0xffffffffu, s, 2);
            if (better(s, c, bv, bi)) { bv = s; bi = c; }
        }
    }
    #pragma unroll
    for (int o = 16; o >= 4; o >>= 1) {
        float ov = __shfl_xor_sync(0xffffffffu, bv, o);
        int   oi = __shfl_xor_sync(0xffffffffu, bi, o);
        if (better(ov, oi, bv, bi)) { bv = ov; bi = oi; }
    }
    if (lane == 0) {
        g_idx[p] = bi;
        atomicAdd(&g_hist[bi], 1);
    }
}

// ---------------------------------------------------------------------------
// K3: gather latents, quantization-loss partial, expand D->C, write out.
// ---------------------------------------------------------------------------
__global__ __launch_bounds__(256) void k_output(const float* __restrict__ ew,
                                                const float* __restrict__ eb,
                                                float* __restrict__ out) {
    __shared__ float lat_s[32][33];
    __shared__ float exp_s[64][32];
    __shared__ float red[256];

    int bh  = blockIdx.x;
    int b   = bh >> 5, h = bh & 31;
    int tid = threadIdx.x;
    int pbase = bh * 32;

    float lsum = 0.f;
    for (int i = tid; i < 1024; i += 256) {
        int ww = i >> 5, d = i & 31;
        int ix = g_idx[pbase + ww];
        float lv = g_e[(size_t)ix * Dd + d];
        lat_s[ww][d] = lv;
        float dz = g_z[((size_t)pbase + ww) * Dd + d] - lv;
        lsum += dz * dz;
    }
    red[tid] = lsum;
    __syncthreads();
    for (int s = 128; s; s >>= 1) {
        if (tid < s) red[tid] += red[tid + s];
        __syncthreads();
    }
    if (tid == 0) g_loss_part[bh] = red[0];

    int w   = tid & 31;
    int cg8 = tid >> 5;

    float latr[32];
    #pragma unroll
    for (int d = 0; d < 32; d++) latr[d] = lat_s[w][d];

    for (int c0 = 0; c0 < Cc; c0 += 64) {
        __syncthreads();
        #pragma unroll
        for (int k = 0; k < 2; k++) {
            int i = tid + 256 * k;           // 0..511
            int cl = i >> 3, v = i & 7;
            *(float4*)&exp_s[cl][v * 4] =
                *(const float4*)(ew + (size_t)(c0 + cl) * Dd + v * 4);
        }
        __syncthreads();
        #pragma unroll
        for (int jj = 0; jj < 8; jj++) {
            int cl = cg8 + 8 * jj;
            int c  = c0 + cl;
            float s = eb[c];
            #pragma unroll
            for (int d4 = 0; d4 < 8; d4++) {
                float4 e4 = *(const float4*)&exp_s[cl][d4 * 4];
                s += e4.x * latr[4*d4] + e4.y * latr[4*d4+1]
                   + e4.z * latr[4*d4+2] + e4.w * latr[4*d4+3];
            }
            out[(((size_t)b * Cc + c) * Hh + h) * Ww + w] = s;
        }
    }
}

// ---------------------------------------------------------------------------
// K4: final scalars — loss mean and perplexity.
// ---------------------------------------------------------------------------
__global__ void k_scalars(float* __restrict__ out, int osz) {
    __shared__ float red[256];
    int tid = threadIdx.x;

    float s = 0.f;
    for (int i = tid; i < 512; i += 256) s += g_loss_part[i];
    red[tid] = s;
    __syncthreads();
    for (int st = 128; st; st >>= 1) {
        if (tid < st) red[tid] += red[tid + st];
        __syncthreads();
    }
    if (tid == 0) out[osz - 2] = red[0] / (float)(Pp * Dd);
    __syncthreads();

    float e = 0.f;
    const float inv = 1.0f / (float)Pp;
    for (int i = tid; i < Nn; i += 256) {
        int c = g_hist[i];
        if (c > 0) {
            float u = (float)c * inv;
            e -= u * logf(u + 1e-6f);
        }
    }
    red[tid] = e;
    __syncthreads();
    for (int st = 128; st; st >>= 1) {
        if (tid < st) red[tid] += red[tid + st];
        __syncthreads();
    }
    if (tid == 0) out[osz - 1] = expf(red[0]);
}

// ---------------------------------------------------------------------------
extern "C" void kernel_launch(void* const* d_in, const int* in_sizes, int n_in,
                              void* d_out, int out_size) {
    const float* enc = (const float*)d_in[0];   // encodings [B,C,H,W]
    const float* emb = (const float*)d_in[1];   // emb_weight [N,D]
    const float* pw  = (const float*)d_in[2];   // proj_w [D,C]
    const float* pb  = (const float*)d_in[3];   // proj_b [D]
    const float* ew  = (const float*)d_in[4];   // exp_w [C,D]
    const float* eb  = (const float*)d_in[5];   // exp_b [C]
    float* out = (float*)d_out;

    cudaFuncSetAttribute(k_sims, cudaFuncAttributeMaxDynamicSharedMemorySize, SIMS_SMEM);

    k_prep_e<<<Nn / 8, 256>>>(emb);
    k_project<<<Bb * Hh, 256>>>(enc, pw, pb);
    k_sims<<<Pp / 64, 256, SIMS_SMEM>>>();
    k_pass2<<<Pp / 8, 256>>>();
    k_output<<<Bb * Hh, 256>>>(ew, eb, out);
    k_scalars<<<1, 256>>>(out, out_size);
}